// round 17
// baseline (speedup 1.0000x reference)
#include <cuda_runtime.h>
#include <cuda_fp16.h>
#include <cstdint>

// CIN_74603581932155 — single-term fp16 GEMM on warp-level mma.sync (HMMA).
// R16 = R15 + latency hiding for the two exposed dependency chains found in
// the R15 post-mortem (tensor 65%, issue 31%, all pipes under 70% => stalls):
//   1. B-input double buffer: the 5 LDS.32 feeding (nj+1)'s B fragments are
//      issued BEFORE nj's HMUL2+MMA burst (29-cyc LDS latency hides under
//      ~60 cyc of MMA issue).
//   2. prefetch.global.L1 of tile kt+1's A-fragment lines at the top of kt
//      (no dest reg, no hazard) so the end-of-tile LDGA L1-hits instead of
//      paying an exposed L2 round trip into kt+1's first MMA.
//
// Architecture (validated R15): B fragments computed IN REGISTERS from
// hid/x0 scalars; A (W) pre-baked in MMA A-fragment layout, LDG.128 from
// L1/L2; no smem U; k-loop touches no shared writes; one WAR barrier between
// k-loop and epilogue per layer.
//
// Per batch-pair CTA:  D(128o x 128col) = W(128 x K) * U^T
//   U[k][col] = hid[h][col] * x0[m][col], k = h*32+m, col = bb*64+d
//   K = 1024 / 4096 / 4096.  fp32 accumulators. W pre-scaled by 2^8 (exact,
//   undone in epilogue) against fp16 subnormals.

namespace {

constexpr int THREADS = 256;
constexpr int NTILE_L0 = 16, NTILE_L12 = 64;
constexpr int NTILES = NTILE_L0 + 2 * NTILE_L12;   // 144
constexpr int XSTR = 40;   // x0T half stride (80B rows)
constexpr int HSTR = 132;  // hidT half stride (264B rows)
constexpr float WSCALE = 256.0f;
constexpr float WINV   = 1.0f / 256.0f;

constexpr int OFF_X0T  = 0;                           // half x0T[128][40]
constexpr int OFF_HIDT = OFF_X0T + 128 * XSTR * 2;    // half hidT[128][132]
constexpr int SMEM_TOTAL = OFF_HIDT + 128 * HSTR * 2; // 44032
static_assert(SMEM_TOTAL <= 115200, "2-CTA smem budget");

// W in A-fragment layout: per tile 4096 uint32:
//   idx = (((kk*4 + ow)*2 + mi)*32 + lane)*4 + j
//   value = half2{ W[o][k], W[o][k+1] } * 2^8, with
//   o = ow*32 + mi*16 + (lane>>2) + (j&1)*8
//   k = tile_k0 + kk*16 + (lane&3)*2 + (j>>1)*8
__device__ __align__(16) uint32_t g_Wfrag[NTILES * 4096];

__device__ __forceinline__ uint32_t smem_u32(const void* p) {
    uint32_t a;
    asm("{ .reg .u64 t; cvta.to.shared.u64 t, %1; cvt.u32.u64 %0, t; }" : "=r"(a) : "l"(p));
    return a;
}

#define LDGA(r, p) \
    asm volatile("ld.global.nc.v4.u32 {%0,%1,%2,%3}, [%4];" \
        : "=r"((r)[0]), "=r"((r)[1]), "=r"((r)[2]), "=r"((r)[3]) : "l"(p))

#define PREFA(p) \
    asm volatile("prefetch.global.L1 [%0];" :: "l"(p))

#define LDS32(r, a) \
    asm volatile("ld.shared.b32 %0, [%1];" : "=r"(r) : "r"(a))

#define MMA16816(d, a, b) \
    asm volatile("mma.sync.aligned.m16n8k16.row.col.f32.f16.f16.f32 " \
        "{%0,%1,%2,%3}, {%4,%5,%6,%7}, {%8,%9}, {%0,%1,%2,%3};" \
        : "+f"((d)[0]), "+f"((d)[1]), "+f"((d)[2]), "+f"((d)[3]) \
        : "r"((a)[0]), "r"((a)[1]), "r"((a)[2]), "r"((a)[3]), "r"((b)[0]), "r"((b)[1]))

// ---------------- prep: W -> fp16 A-fragment layout (pre-scaled by 256) -------
__global__ void prep_w_kernel(const float* __restrict__ W0,
                              const float* __restrict__ W1,
                              const float* __restrict__ W2)
{
    int tile = blockIdx.x;              // 0..143
    int tb; const float* Ws; int K;
    if (tile < NTILE_L0)      { tb = tile;            Ws = W0; K = 1024; }
    else if (tile < 80)       { tb = tile - NTILE_L0; Ws = W1; K = 4096; }
    else                      { tb = tile - 80;       Ws = W2; K = 4096; }

    uint32_t* dst = g_Wfrag + (size_t)tile * 4096;
    for (int i = threadIdx.x; i < 4096; i += blockDim.x) {
        int j    = i & 3;
        int lane = (i >> 2) & 31;
        int mi   = (i >> 7) & 1;
        int ow   = (i >> 8) & 3;
        int kk   = (i >> 10) & 3;
        int o  = ow * 32 + mi * 16 + (lane >> 2) + (j & 1) * 8;
        int kc = kk * 16 + (lane & 3) * 2 + ((j >> 1) & 1) * 8;
        const float* wp = Ws + (size_t)o * K + (size_t)tb * 64 + kc;
        __half2 h = __floats2half2_rn(wp[0] * WSCALE, wp[1] * WSCALE);
        dst[i] = *reinterpret_cast<uint32_t*>(&h);
    }
}

// ---------------- main kernel --------------------------------------------------
__global__ void __launch_bounds__(THREADS, 2)
cin_mma_kernel(const float* __restrict__ x,
               const float* __restrict__ bias0,
               const float* __restrict__ bias1,
               const float* __restrict__ bias2,
               float* __restrict__ out)
{
    extern __shared__ char smem[];
    const uint32_t sb = smem_u32(smem);
    const int tid = threadIdx.x;
    const int wid = tid >> 5;
    const int lane = tid & 31;
    const int b0 = blockIdx.x * 2;

    __half* x0T  = reinterpret_cast<__half*>(smem + OFF_X0T);
    __half* hidT = reinterpret_cast<__half*>(smem + OFF_HIDT);

    // ---- build x0T[col][m] (fp16), col = bb*64 + d ----
    {
        const float* xg = x + (size_t)b0 * 2048;
        #pragma unroll
        for (int r = 0; r < 4; ++r) {
            int idx4 = tid + THREADS * r;           // 0..1023 float4s
            int bb = idx4 >> 9, rem = idx4 & 511;
            int m = rem >> 4, d4 = rem & 15;
            float4 v = *reinterpret_cast<const float4*>(xg + bb * 2048 + m * 64 + d4 * 4);
            int col0 = bb * 64 + d4 * 4;
            x0T[(col0 + 0) * XSTR + m] = __float2half_rn(v.x);
            x0T[(col0 + 1) * XSTR + m] = __float2half_rn(v.y);
            x0T[(col0 + 2) * XSTR + m] = __float2half_rn(v.z);
            x0T[(col0 + 3) * XSTR + m] = __float2half_rn(v.w);
        }
    }
    __syncthreads();

    // ---- per-warp tile mapping: 4(o) x 2(col) warps, warp tile 32 x 64 ----
    const int ow = wid & 3, cw = wid >> 2;
    const int o_base = ow * 32;
    const int col_base = cw * 64;

    // per-thread B-gen column (n = lane>>2 within nj-group)
    const int colq = col_base + (lane >> 2);
    const uint32_t xaddr0 = sb + OFF_X0T
                          + (uint32_t)colq * (XSTR * 2) + (uint32_t)(lane & 3) * 4;

    // per-warp A-fragment base (bytes)
    const unsigned char* abase = reinterpret_cast<const unsigned char*>(g_Wfrag)
                               + (size_t)ow * 1024 + (size_t)lane * 16;

    const float* biases[3] = {bias0, bias1, bias2};
    const int nk_l[3] = {NTILE_L0, NTILE_L12, NTILE_L12};
    const int tb_l[3] = {0, NTILE_L0, NTILE_L0 + NTILE_L12};

    for (int layer = 0; layer < 3; ++layer) {
        const int nk = nk_l[layer];
        const uint32_t hbase = (layer == 0) ? (sb + OFF_X0T) : (sb + OFF_HIDT);
        const int hstrB = ((layer == 0) ? XSTR : HSTR) * 2;
        const uint32_t haddr0 = hbase + (uint32_t)colq * hstrB;

        float acc[2][8][4];
        #pragma unroll
        for (int mi = 0; mi < 2; ++mi)
            #pragma unroll
            for (int nj = 0; nj < 8; ++nj)
                #pragma unroll
                for (int q = 0; q < 4; ++q) acc[mi][nj][q] = 0.0f;

        // A fragments for the whole 64-k tile: [kk][mi][4]
        uint32_t A[4][2][4];
        auto lda_tile = [&](int t) {
            const unsigned char* p = abase + (size_t)(tb_l[layer] + t) * 16384;
            #pragma unroll
            for (int kk = 0; kk < 4; ++kk) {
                LDGA(A[kk][0], p + kk * 4096);
                LDGA(A[kk][1], p + kk * 4096 + 512);
            }
        };
        lda_tile(0);

        // B-input loader: 5 LDS.32 for step (kt, nj)
        auto ldB = [&](int kt, int nj, uint32_t& H, uint32_t* X) {
            const uint32_t ha = haddr0 + (uint32_t)kt * 4
                              + (uint32_t)nj * (uint32_t)(8 * hstrB);
            const uint32_t xa = xaddr0 + (uint32_t)nj * (8 * XSTR * 2);
            LDS32(H, ha);
            LDS32(X[0], xa);
            LDS32(X[1], xa + 16);
            LDS32(X[2], xa + 32);
            LDS32(X[3], xa + 48);
        };

        uint32_t curH, curX[4], nxtH, nxtX[4];
        ldB(0, 0, curH, curX);

        // ---- main loop: no barriers; B inputs double-buffered ----
        for (int kt = 0; kt < nk; ++kt) {
            const bool more = (kt + 1 < nk);

            // prefetch next tile's A lines into L1 (no dest reg, no hazard)
            if (more) {
                const unsigned char* p = abase + (size_t)(tb_l[layer] + kt + 1) * 16384;
                #pragma unroll
                for (int kk = 0; kk < 4; ++kk) {
                    PREFA(p + kk * 4096);
                    PREFA(p + kk * 4096 + 512);
                }
            }

            #pragma unroll
            for (int nj = 0; nj < 8; ++nj) {
                // prefetch B inputs for the NEXT step before this step's math
                if (nj < 7)      ldB(kt, nj + 1, nxtH, nxtX);
                else if (more)   ldB(kt + 1, 0, nxtH, nxtX);

                __half2 hh = *reinterpret_cast<__half2*>(&curH);
                __half2 hb[2] = { __half2half2(__low2half(hh)),
                                  __half2half2(__high2half(hh)) };

                #pragma unroll
                for (int hhalf = 0; hhalf < 2; ++hhalf) {
                    #pragma unroll
                    for (int mhalf = 0; mhalf < 2; ++mhalf) {
                        const int kk = hhalf * 2 + mhalf;
                        __half2 u0 = __hmul2(hb[hhalf],
                                             *reinterpret_cast<__half2*>(&curX[2 * mhalf]));
                        __half2 u1 = __hmul2(hb[hhalf],
                                             *reinterpret_cast<__half2*>(&curX[2 * mhalf + 1]));
                        uint32_t b[2] = { *reinterpret_cast<uint32_t*>(&u0),
                                          *reinterpret_cast<uint32_t*>(&u1) };
                        MMA16816(acc[0][nj], A[kk][0], b);
                        MMA16816(acc[1][nj], A[kk][1], b);
                    }
                }

                // rotate double buffer (renamed away under full unroll)
                curH = nxtH;
                #pragma unroll
                for (int q = 0; q < 4; ++q) curX[q] = nxtX[q];
            }
            // reload A for kt+1 (prefetched above -> L1 hit)
            if (more) lda_tile(kt + 1);
        }

        // WAR barrier: all warps finish READING hidT/x0T before epilogue
        // overwrites hidT in place.
        __syncthreads();

        // ---- epilogue: unscale + bias + ReLU, fp16 hidT store, d-sum ----
        {
            const float* bl = biases[layer];
            #pragma unroll
            for (int mi = 0; mi < 2; ++mi) {
                #pragma unroll
                for (int s = 0; s < 2; ++s) {
                    const int h = o_base + mi * 16 + (lane >> 2) + 8 * s;
                    const float bv = __ldg(&bl[h]);
                    float rs = 0.0f;
                    #pragma unroll
                    for (int nj = 0; nj < 8; ++nj) {
                        float z0 = fmaxf(acc[mi][nj][2 * s] * WINV + bv, 0.0f);
                        float z1 = fmaxf(acc[mi][nj][2 * s + 1] * WINV + bv, 0.0f);
                        rs += z0 + z1;
                        if (layer < 2) {
                            int c0 = col_base + nj * 8 + (lane & 3) * 2;
                            hidT[c0 * HSTR + h] = __float2half_rn(z0);
                            hidT[(c0 + 1) * HSTR + h] = __float2half_rn(z1);
                        }
                    }
                    rs += __shfl_xor_sync(0xFFFFFFFFu, rs, 1);
                    rs += __shfl_xor_sync(0xFFFFFFFFu, rs, 2);
                    if ((lane & 3) == 0)
                        out[(size_t)(b0 + cw) * 384 + layer * 128 + h] = rs;
                }
            }
        }
        __syncthreads();   // hidT complete before next layer's B-gen reads
    }
}

} // namespace

extern "C" void kernel_launch(void* const* d_in, const int* in_sizes, int n_in,
                              void* d_out, int out_size) {
    const float* x  = (const float*)d_in[0];
    const float* W0 = (const float*)d_in[1];
    const float* b0 = (const float*)d_in[2];
    const float* W1 = (const float*)d_in[3];
    const float* b1 = (const float*)d_in[4];
    const float* W2 = (const float*)d_in[5];
    const float* b2 = (const float*)d_in[6];
    float* out = (float*)d_out;

    prep_w_kernel<<<NTILES, 256>>>(W0, W1, W2);

    cudaFuncSetAttribute(cin_mma_kernel, cudaFuncAttributeMaxDynamicSharedMemorySize,
                         SMEM_TOTAL);
    cin_mma_kernel<<<512, THREADS, SMEM_TOTAL>>>(x, b0, b1, b2, out);
}